// round 5
// baseline (speedup 1.0000x reference)
#include <cuda_runtime.h>

// ---------------- problem constants ----------------
#define BB      256
#define TT      50
#define IDD     16
#define NCV     32
#define D0V     512
#define DINV    528
#define HIDV    512
#define NSTEPS  5
#define DT_C    0.05f

#define HS      1056            // padded row stride of h (1040 used; pad stays zero)
#define G_CTAS  136             // 8 groups x 17 CTAs
#define NTHR    128

// ---------------- dynamic smem layout (floats) ----------------
// Wq: per k-pair kp, 16 quads {w_k(2c), w_k(2c+1), w_k1(2c), w_k1(2c+1)}
// W1: 272 kp x 64 ; W2: 256 kp x 64 ; W3: 256 kp x 64
// Xd: double buffer, per 32-k chunk: 16 kp x (32 rows x dup quad), kp stride 132
#define WS1_OFF 0
#define WS2_OFF (272 * 64)                    // 17408
#define WS3_OFF (WS2_OFF + 256 * 64)          // 33792
#define XD_OFF  (WS3_OFF + 256 * 64)          // 50176
#define XD_BUF  (16 * 132)                    // 2112 floats per chunk buffer
#define SMEM_FLOATS (XD_OFF + 2 * XD_BUF)     // 54400
#define SMEM_BYTES  (SMEM_FLOATS * 4)         // 217600 B (< 227KB opt-in)

// ---------------- device scratch ----------------
__device__ float g_h[2][BB * HS];
__device__ float g_a0[BB * HIDV];
__device__ float g_a1[BB * HIDV];
__device__ int   g_tlast;
__device__ unsigned g_cnt[8 * 32];
__device__ volatile unsigned g_gen[8 * 32];

// ---------------- per-group barrier (17 CTAs, co-resident) ----------------
__device__ __forceinline__ void group_sync(int rb) {
    __syncthreads();
    if (threadIdx.x == 0) {
        const int s = rb * 32;
        unsigned gen = g_gen[s];
        __threadfence();
        if (atomicAdd(&g_cnt[s], 1u) == 16u) {
            g_cnt[s] = 0u;
            __threadfence();
            g_gen[s] = gen + 1u;
        } else {
            while (g_gen[s] == gen) { }
        }
        __threadfence();
    }
    __syncthreads();
}

// ---------------- f32x2 helpers ----------------
__device__ __forceinline__ void ffma2_acc(unsigned long long& acc,
                                          unsigned long long a,
                                          unsigned long long b) {
    asm("fma.rn.f32x2 %0, %1, %2, %0;" : "+l"(acc) : "l"(a), "l"(b));
}
__device__ __forceinline__ void unpack2(unsigned long long v, float& lo, float& hi) {
    asm("mov.b64 {%0, %1}, %2;" : "=f"(lo), "=f"(hi) : "l"(v));
}

struct U2x2 { unsigned long long lo, hi; };
__device__ __forceinline__ U2x2 lds128_u2(const float* p) {
    U2x2 r;
    asm("ld.shared.v2.b64 {%0, %1}, [%2];"
        : "=l"(r.lo), "=l"(r.hi) : "l"((unsigned long long)__cvta_generic_to_shared(p)));
    return r;
}

// ---------------- GEMM phase: 32x32 tile, 128 threads, 2x4 per thread -------
// MODE 0/1: outbuf[row*512 + col] = relu(X@W + bias)
// MODE 2  : hn[row*HS + 512+col] = hc[row*HS + 512+col] + DT*(X@W + bias), col<528
template <int MODE>
__device__ __forceinline__ void gemm_phase(const float* __restrict__ X, int xs, int nkc,
                                           const float* __restrict__ Wq,
                                           const float* __restrict__ bias,
                                           float* __restrict__ outbuf,
                                           const float* __restrict__ hc,
                                           float* __restrict__ hn,
                                           float* __restrict__ Xd,
                                           int r0, int c0) {
    const int tid = threadIdx.x;
    // loader: lrow 0..31, lq 0..3 ; each thread: 2 float4 per chunk (k-quads lq, lq+4)
    const int lrow = tid >> 2;
    const int lq   = tid & 3;
    // compute: rows 2tr, 2tr+1 ; cols 4tc .. 4tc+3
    const int tr = tid >> 3;          // 0..15
    const int tc = tid & 7;           // 0..7

    const float* xrow = X + (r0 + lrow) * xs + lq * 4;

    unsigned long long aA0 = 0ull, aA1 = 0ull, aB0 = 0ull, aB1 = 0ull;

    float4 pa = *(const float4*)(xrow);
    float4 pb = *(const float4*)(xrow + 16);
    {
        float* d = Xd;
        *(float4*)(d + (2 * lq + 0) * 132 + lrow * 4) = make_float4(pa.x, pa.x, pa.y, pa.y);
        *(float4*)(d + (2 * lq + 1) * 132 + lrow * 4) = make_float4(pa.z, pa.z, pa.w, pa.w);
        *(float4*)(d + (2 * lq + 8) * 132 + lrow * 4) = make_float4(pb.x, pb.x, pb.y, pb.y);
        *(float4*)(d + (2 * lq + 9) * 132 + lrow * 4) = make_float4(pb.z, pb.z, pb.w, pb.w);
    }
    if (nkc > 1) {
        pa = *(const float4*)(xrow + 32);
        pb = *(const float4*)(xrow + 48);
    }
    __syncthreads();

    for (int kc = 0; kc < nkc; kc++) {
        if (kc + 1 < nkc) {
            float* d = Xd + ((kc + 1) & 1) * XD_BUF;
            *(float4*)(d + (2 * lq + 0) * 132 + lrow * 4) = make_float4(pa.x, pa.x, pa.y, pa.y);
            *(float4*)(d + (2 * lq + 1) * 132 + lrow * 4) = make_float4(pa.z, pa.z, pa.w, pa.w);
            *(float4*)(d + (2 * lq + 8) * 132 + lrow * 4) = make_float4(pb.x, pb.x, pb.y, pb.y);
            *(float4*)(d + (2 * lq + 9) * 132 + lrow * 4) = make_float4(pb.z, pb.z, pb.w, pb.w);
        }
        if (kc + 2 < nkc) {
            pa = *(const float4*)(xrow + (kc + 2) * 32);
            pb = *(const float4*)(xrow + (kc + 2) * 32 + 16);
        }

        const float* xb = Xd + (kc & 1) * XD_BUF + 2 * tr * 4;
        const float* wb = Wq + kc * (16 * 64) + 2 * tc * 4;
        #pragma unroll
        for (int kp = 0; kp < 16; kp++) {
            U2x2 x0 = lds128_u2(xb + kp * 132);        // {x_k(r) dup | x_k1(r) dup}
            U2x2 x1 = lds128_u2(xb + kp * 132 + 4);    // row r+1
            U2x2 w0 = lds128_u2(wb + kp * 64);         // {w_k(c0,c0+1) | w_k1(c0,c0+1)}
            U2x2 w1 = lds128_u2(wb + kp * 64 + 4);     // cols c0+2, c0+3
            ffma2_acc(aA0, x0.lo, w0.lo);
            ffma2_acc(aA0, x0.hi, w0.hi);
            ffma2_acc(aA1, x0.lo, w1.lo);
            ffma2_acc(aA1, x0.hi, w1.hi);
            ffma2_acc(aB0, x1.lo, w0.lo);
            ffma2_acc(aB0, x1.hi, w0.hi);
            ffma2_acc(aB1, x1.lo, w1.lo);
            ffma2_acc(aB1, x1.hi, w1.hi);
        }
        __syncthreads();
    }

    float oA0, oA1, oA2, oA3, oB0, oB1, oB2, oB3;
    unpack2(aA0, oA0, oA1); unpack2(aA1, oA2, oA3);
    unpack2(aB0, oB0, oB1); unpack2(aB1, oB2, oB3);

    const int ra = r0 + 2 * tr;
    const int ca = c0 + 4 * tc;
    if (MODE != 2) {
        float4 bv = *(const float4*)&bias[ca];
        *(float4*)&outbuf[ra * 512 + ca] =
            make_float4(fmaxf(oA0 + bv.x, 0.f), fmaxf(oA1 + bv.y, 0.f),
                        fmaxf(oA2 + bv.z, 0.f), fmaxf(oA3 + bv.w, 0.f));
        *(float4*)&outbuf[(ra + 1) * 512 + ca] =
            make_float4(fmaxf(oB0 + bv.x, 0.f), fmaxf(oB1 + bv.y, 0.f),
                        fmaxf(oB2 + bv.z, 0.f), fmaxf(oB3 + bv.w, 0.f));
    } else {
        if (ca < DINV) {      // boundary is float4-aligned (528-512=16)
            float4 bv = *(const float4*)&bias[ca];
            float4 h0 = *(const float4*)&hc[ra * HS + 512 + ca];
            float4 h1 = *(const float4*)&hc[(ra + 1) * HS + 512 + ca];
            *(float4*)&hn[ra * HS + 512 + ca] =
                make_float4(h0.x + DT_C * (oA0 + bv.x), h0.y + DT_C * (oA1 + bv.y),
                            h0.z + DT_C * (oA2 + bv.z), h0.w + DT_C * (oA3 + bv.w));
            *(float4*)&hn[(ra + 1) * HS + 512 + ca] =
                make_float4(h1.x + DT_C * (oB0 + bv.x), h1.y + DT_C * (oB1 + bv.y),
                            h1.z + DT_C * (oB2 + bv.z), h1.w + DT_C * (oB3 + bv.w));
        }
    }
}

// ---------------- cn0 ODE phase (j==16 CTA; A/Bv cached in its W1 region) ----
__device__ __forceinline__ void cnode_phase(int rb,
                                            const float* __restrict__ hc,
                                            float* __restrict__ hn,
                                            const float* __restrict__ As,
                                            const float* __restrict__ Bs) {
    const int tid = threadIdx.x;
    const int b0 = rb * 32;
    #pragma unroll
    for (int rep = 0; rep < 4; rep++) {
        const int item = rep * NTHR + tid;      // 0..511
        const int b = b0 + (item >> 4);
        const int i = item & 15;
        const float* hr = hc + b * HS;
        float x[32];
        const float4* cp = (const float4*)(hr + i * 32);
        #pragma unroll
        for (int q = 0; q < 8; q++) {
            float4 v = cp[q];
            x[4 * q] = v.x; x[4 * q + 1] = v.y; x[4 * q + 2] = v.z; x[4 * q + 3] = v.w;
        }
        const float cn1v = hr[512 + i];
        float* outp = hn + b * HS + i * 32;
        #pragma unroll 4
        for (int n = 0; n < 32; n++) {
            float acc = Bs[n] * cn1v;
            const float4* ap = (const float4*)(As + n * 32);
            #pragma unroll
            for (int q = 0; q < 8; q++) {
                float4 a4 = ap[q];
                acc = fmaf(x[4 * q], a4.x, acc);
                acc = fmaf(x[4 * q + 1], a4.y, acc);
                acc = fmaf(x[4 * q + 2], a4.z, acc);
                acc = fmaf(x[4 * q + 3], a4.w, acc);
            }
            outp[n] = x[n] + DT_C * acc;
        }
    }
}

// ---------------- observation update (group-local) ----------------
__device__ __forceinline__ void obs_phase(int rb, int j, int t,
                                          const float* __restrict__ Y,
                                          const float* __restrict__ mask,
                                          float* __restrict__ h,
                                          float* __restrict__ out,
                                          long off_traj, long off_lasth, int tlast) {
    const int gid = j * NTHR + threadIdx.x;
    const int nth = 17 * NTHR;
    const int b0 = rb * 32;
    for (int idx = gid; idx < 32 * DINV; idx += nth) {
        const int b = b0 + idx / DINV;
        const int c = idx % DINV;
        const float m = mask[b * TT + t];
        float* hr = h + b * HS;
        const float he = hr[512 + c];
        if (c < IDD) {
            const long po = (long)(b * TT + t) * IDD + c;
            out[po] = he;
            if (off_traj >= 0) out[off_traj + po] = he;
            const float y = Y[(b * TT + t) * IDD + c];
            hr[512 + c] = m * y + (1.f - m) * he;
        } else {
            const int jj = c - IDD;
            hr[512 + c] = m * hr[jj] + (1.f - m) * he;
        }
    }
    if (t == tlast) {
        for (int idx = gid; idx < 32 * D0V; idx += nth) {
            const int b = b0 + (idx >> 9);
            const int jj = idx & 511;
            out[off_lasth + (long)b * D0V + jj] = h[b * HS + jj];
        }
    }
}

// ---------------- persistent kernel ----------------
__global__ void __launch_bounds__(NTHR, 1)
cnode_persistent(const float* __restrict__ Y, const float* __restrict__ mask,
                 const float* __restrict__ A, const float* __restrict__ Bv,
                 const float* __restrict__ W1, const float* __restrict__ b1,
                 const float* __restrict__ W2, const float* __restrict__ b2,
                 const float* __restrict__ W3, const float* __restrict__ b3,
                 float* __restrict__ out,
                 long off_traj, long off_lasth, long off_hfin) {
    extern __shared__ float sm[];
    const int cta = blockIdx.x;
    const int tid = threadIdx.x;
    const int rb = cta / 17;          // row block 0..7 (batch rows rb*32..+31)
    const int j  = cta - rb * 17;     // 0..16
    const int r0 = rb * 32;
    const int c0 = j * 32;            // col tile origin (j==16 -> 512, GEMM3 only)

    // ---- load resident weights (k-paired quad layout) ----
    if (j < 16) {
        for (int idx = tid; idx < 272 * 64; idx += NTHR) {
            const int kp = idx >> 6, r = idx & 63;
            const int tcq = r >> 2, e = r & 3;
            const int k = 2 * kp + (e >> 1);
            const int c = c0 + 2 * tcq + (e & 1);
            sm[WS1_OFF + idx] = (k < DINV) ? W1[k * HIDV + c] : 0.f;
        }
        for (int idx = tid; idx < 256 * 64; idx += NTHR) {
            const int kp = idx >> 6, r = idx & 63;
            const int tcq = r >> 2, e = r & 3;
            const int k = 2 * kp + (e >> 1);
            const int c = c0 + 2 * tcq + (e & 1);
            sm[WS2_OFF + idx] = W2[k * HIDV + c];
        }
    } else {
        // cn_ode CTA: cache A (transposed access pattern = row-major as used) + Bv
        for (int i = tid; i < NCV * NCV; i += NTHR) sm[WS1_OFF + i] = A[i];
        for (int i = tid; i < NCV; i += NTHR) sm[WS1_OFF + 1024 + i] = Bv[i];
    }
    for (int idx = tid; idx < 256 * 64; idx += NTHR) {
        const int kp = idx >> 6, r = idx & 63;
        const int tcq = r >> 2, e = r & 3;
        const int k = 2 * kp + (e >> 1);
        const int c = c0 + 2 * tcq + (e & 1);
        sm[WS3_OFF + idx] = (c < DINV) ? W3[k * DINV + c] : 0.f;
    }
    __syncthreads();

    float* Xd = sm + XD_OFF;

    int cur = 0;
    const int tlast = g_tlast;
    for (int t = 0; t < TT; t++) {
        for (int s = 0; s < NSTEPS; s++) {
            float* hc = g_h[cur];
            float* hn = g_h[cur ^ 1];
            // phase 1: GEMM1 (K=544 padded, 17 chunks) on j<16 ; cn_ode on j==16
            if (j < 16)
                gemm_phase<0>(hc + 512, HS, 17, sm + WS1_OFF, b1, g_a0,
                              nullptr, nullptr, Xd, r0, c0);
            else
                cnode_phase(rb, hc, hn, sm + WS1_OFF, sm + WS1_OFF + 1024);
            group_sync(rb);
            // phase 2: GEMM2 (K=512)
            if (j < 16)
                gemm_phase<1>(g_a0, HIDV, 16, sm + WS2_OFF, b2, g_a1,
                              nullptr, nullptr, Xd, r0, c0);
            group_sync(rb);
            // phase 3: GEMM3 (K=512) + euler update of cn1 part (all 17)
            gemm_phase<2>(g_a1, HIDV, 16, sm + WS3_OFF, b3, nullptr,
                          hc, hn, Xd, r0, c0);
            group_sync(rb);
            cur ^= 1;
        }
        obs_phase(rb, j, t, Y, mask, g_h[cur], out, off_traj, off_lasth, tlast);
        group_sync(rb);
    }
    // h_fin copy (group-local rows)
    const int gid = j * NTHR + tid;
    const float* h = g_h[cur];
    for (int idx = gid; idx < 32 * 1040; idx += 17 * NTHR) {
        const int b = rb * 32 + idx / 1040;
        const int c = idx % 1040;
        out[off_hfin + (long)b * 1040 + c] = h[b * HS + c];
    }
}

// ---------------- init kernels ----------------
__global__ void init_kernel(const float* __restrict__ times, float* __restrict__ out,
                            long off_times, long off_lasth) {
    const int gtid = blockIdx.x * blockDim.x + threadIdx.x;
    const int nth = gridDim.x * blockDim.x;
    float* hall = &g_h[0][0];
    for (int i = gtid; i < 2 * BB * HS; i += nth) hall[i] = 0.f;
    for (int i = gtid; i < BB * D0V; i += nth) out[off_lasth + i] = 0.f;
    if (gtid < TT) out[off_times + gtid] = times[gtid];
    if (gtid < 8 * 32) { g_cnt[gtid] = 0u; g_gen[gtid] = 0u; }
}

__global__ void tlast_kernel(const float* __restrict__ mask) {
    __shared__ int anyt[TT];
    const int tid = threadIdx.x;
    if (tid < TT) {
        int a = 0;
        for (int b = 0; b < BB; b++)
            if (mask[b * TT + tid] > 0.f) { a = 1; break; }
        anyt[tid] = a;
    }
    __syncthreads();
    if (tid == 0) {
        int tl = -1;
        for (int t = TT - 1; t >= 0; t--)
            if (anyt[t]) { tl = t; break; }
        g_tlast = tl;
    }
}

// ---------------- launch ----------------
extern "C" void kernel_launch(void* const* d_in, const int* in_sizes, int n_in,
                              void* d_out, int out_size) {
    const float* times = (const float*)d_in[0];
    const float* Y     = (const float*)d_in[1];
    const float* mask  = (const float*)d_in[2];
    const float* A     = (const float*)d_in[3];
    const float* Bv    = (const float*)d_in[4];
    const float* W1    = (const float*)d_in[5];
    const float* b1    = (const float*)d_in[6];
    const float* W2    = (const float*)d_in[7];
    const float* b2    = (const float*)d_in[8];
    const float* W3    = (const float*)d_in[9];
    const float* b3    = (const float*)d_in[10];
    float* out = (float*)d_out;

    cudaFuncSetAttribute(cnode_persistent,
                         cudaFuncAttributeMaxDynamicSharedMemorySize, SMEM_BYTES);

    const long np = (long)BB * TT * IDD;          // 204800
    long off_traj, off_times, off_lasth, off_hfin;
    const long full = 2 * np + TT + (long)BB * D0V + (long)BB * (2 * D0V + IDD);
    if ((long)out_size >= full) {
        off_traj = np;
        off_times = 2 * np;
    } else {
        off_traj = -1;
        off_times = np;
    }
    off_lasth = off_times + TT;
    off_hfin = off_lasth + (long)BB * D0V;

    init_kernel<<<64, 256>>>(times, out, off_times, off_lasth);
    tlast_kernel<<<1, 64>>>(mask);
    cnode_persistent<<<G_CTAS, NTHR, SMEM_BYTES>>>(Y, mask, A, Bv, W1, b1, W2, b2, W3, b3,
                                                   out, off_traj, off_lasth, off_hfin);
}